// round 7
// baseline (speedup 1.0000x reference)
#include <cuda_runtime.h>
#include <cstdint>

#define NS 13824            // D*H*W = 24*24*24
#define NB 2                // batch
#define NC 64               // channels
#define NVOX (NB * NS)      // 27648 voxels
#define PD 26               // padded dim
#define PD2 (PD * PD)       // 676
#define P3 (PD * PD * PD)   // 17576 padded voxels per batch
#define NBORD 3752          // border voxels per batch = P3 - NS
#define NPROJ (NVOX / 64)   // 432 projection blocks
#define NZERO ((NB * NBORD * 16) / 256)   // 469 border-zero blocks

// q unpadded voxel-major [n][c]; k,v zero-padded [b][dp][hp][wp][c]
__device__ float g_q [NVOX * NC];
__device__ float g_kp[NB * P3 * NC];
__device__ float g_vp[NB * P3 * NC];

typedef unsigned long long u64;

__device__ __forceinline__ u64 pack2(float lo, float hi) {
    u64 r; asm("mov.b64 %0,{%1,%2};" : "=l"(r) : "f"(lo), "f"(hi)); return r;
}
__device__ __forceinline__ float2 unpack2(u64 v) {
    float2 r; asm("mov.b64 {%0,%1},%2;" : "=f"(r.x), "=f"(r.y) : "l"(v)); return r;
}
__device__ __forceinline__ u64 fma2(u64 a, u64 b, u64 c) {
    u64 d; asm("fma.rn.f32x2 %0,%1,%2,%3;" : "=l"(d) : "l"(a), "l"(b), "l"(c)); return d;
}

// ---------------------------------------------------------------------------
// Kernel 1: QKV projection + (tail blocks) border zeroing.
// Blocks [0, NPROJ): projection, 64 voxels each.
// Blocks [NPROJ, NPROJ+NZERO): zero the 3752 border voxels/batch of g_kp/g_vp.
// ---------------------------------------------------------------------------
__global__ __launch_bounds__(256) void k_proj(
    const float* __restrict__ x,
    const float* __restrict__ Wq, const float* __restrict__ bq,
    const float* __restrict__ Wk, const float* __restrict__ bk,
    const float* __restrict__ Wv, const float* __restrict__ bv)
{
    __shared__ __align__(16) float WTs[64 * 68];   // WTs[j*68 + c] = W[c][j]
    __shared__ __align__(16) float Xs[64 * 64];    // Xs[j*64 + t]

    const int tid = threadIdx.x;

    if (blockIdx.x >= NPROJ) {
        // ---- border zeroing tail blocks ----
        int idx = (blockIdx.x - NPROJ) * 256 + tid;   // [0, NB*NBORD*16)
        int t  = idx >> 4;
        int c4 = (idx & 15) * 4;
        int bb = t / NBORD;
        int r  = t % NBORD;

        int dp, hp, wp;
        if (r < 1352) {                   // faces dp = 0 / 25
            dp = (r >= 676) ? 25 : 0;
            int q = (r >= 676) ? r - 676 : r;
            hp = q / PD; wp = q % PD;
        } else if (r < 2600) {            // faces hp = 0 / 25
            int q = r - 1352;
            dp = 1 + q / 52;
            int q2 = q % 52;
            hp = (q2 >= 26) ? 25 : 0;
            wp = (q2 >= 26) ? q2 - 26 : q2;
        } else {                          // faces wp = 0 / 25
            int q = r - 2600;
            dp = 1 + q / 48;
            int q2 = q % 48;
            hp = 1 + (q2 >> 1);
            wp = (q2 & 1) ? 25 : 0;
        }

        long vox = (long)bb * P3 + dp * PD2 + hp * PD + wp;
        float4 z = make_float4(0.f, 0.f, 0.f, 0.f);
        *(float4*)&g_kp[vox * NC + c4] = z;
        *(float4*)&g_vp[vox * NC + c4] = z;
        return;
    }

    // ---- projection blocks ----
    const int lane = tid & 31;
    const int wid  = tid >> 5;
    const int tile = blockIdx.x;               // 0..431
    const int bb   = tile / (NS / 64);
    const int s0   = (tile % (NS / 64)) * 64;

    const float* xb = x + (long)bb * NC * NS + s0;

#pragma unroll
    for (int k = 0; k < 16; k++) {
        int idx = tid + k * 256;
        int j = idx >> 6, u = idx & 63;
        Xs[j * 64 + u] = xb[(long)j * NS + u];
    }

    const int c0  = (wid & 1) * 32 + (lane >> 2) * 4;
    const int tv0 = (wid >> 1) * 16 + (lane & 3) * 4;

    // output addresses for the 4-voxel run (w-aligned: never wraps a row)
    const int sA = s0 + tv0;
    const int d  = sA / 576, h = (sA / 24) % 24, w0 = sA % 24;
    const long nq  = (long)(bb * NS + sA) * NC + c0;
    const long npk = ((long)bb * P3 + (d + 1) * PD2 + (h + 1) * PD + (w0 + 1)) * NC + c0;

    const float* Wsrc[3] = {Wq, Wk, Wv};
    const float* bsrc[3] = {bq, bk, bv};

#pragma unroll
    for (int m = 0; m < 3; m++) {
        __syncthreads();
        const float* W = Wsrc[m];
#pragma unroll
        for (int k2 = 0; k2 < 16; k2++) {
            int idx = tid + k2 * 256;
            int c = idx >> 6, j = idx & 63;
            WTs[j * 68 + c] = W[idx];
        }
        __syncthreads();

        const float4 bv4 = *(const float4*)&bsrc[m][c0];
        u64 acc[4][2];
#pragma unroll
        for (int t = 0; t < 4; t++) {
            acc[t][0] = pack2(bv4.x, bv4.y);
            acc[t][1] = pack2(bv4.z, bv4.w);
        }

#pragma unroll 8
        for (int j = 0; j < 64; j++) {
            ulonglong2 w = *(const ulonglong2*)&WTs[j * 68 + c0];
            float4 xv = *(const float4*)&Xs[j * 64 + tv0];
            u64 xd0 = pack2(xv.x, xv.x);
            u64 xd1 = pack2(xv.y, xv.y);
            u64 xd2 = pack2(xv.z, xv.z);
            u64 xd3 = pack2(xv.w, xv.w);
            acc[0][0] = fma2(w.x, xd0, acc[0][0]);
            acc[0][1] = fma2(w.y, xd0, acc[0][1]);
            acc[1][0] = fma2(w.x, xd1, acc[1][0]);
            acc[1][1] = fma2(w.y, xd1, acc[1][1]);
            acc[2][0] = fma2(w.x, xd2, acc[2][0]);
            acc[2][1] = fma2(w.y, xd2, acc[2][1]);
            acc[3][0] = fma2(w.x, xd3, acc[3][0]);
            acc[3][1] = fma2(w.y, xd3, acc[3][1]);
        }

        if (m == 0) {
#pragma unroll
            for (int t = 0; t < 4; t++) {
                float2 a = unpack2(acc[t][0]);
                float2 b = unpack2(acc[t][1]);
                float4 o;                     // q pre-scaled by hd^-0.5 = 0.25
                o.x = a.x * 0.25f; o.y = a.y * 0.25f;
                o.z = b.x * 0.25f; o.w = b.y * 0.25f;
                *(float4*)&g_q[nq + (long)t * NC] = o;
            }
        } else {
            float* g = (m == 1) ? g_kp : g_vp;
#pragma unroll
            for (int t = 0; t < 4; t++) {
                float2 a = unpack2(acc[t][0]);
                float2 b = unpack2(acc[t][1]);
                float4 o; o.x = a.x; o.y = a.y; o.z = b.x; o.w = b.y;
                *(float4*)&g[npk + (long)t * NC] = o;
            }
        }
    }
}

// ---------------------------------------------------------------------------
// Kernel 2: 3x3x3 local attention + residual (R5 version: row-interleaved).
// Thread handles FOUR consecutive-w queries (sliding window): per (di,hi)
// plane, the 6-wide k/v row is loaded once; each k_j/v_j serves up to 3
// queries -> 27 loads/query and 4 independent softmax chains for ILP, with
// only one k/v row live at a time (low register pressure).
// 16 lanes per query-group; lane owns 4 contiguous channels (LDG.128).
// Quad = head; 2 shfls finish the 16-dim dot. Single-pass softmax
// (shift-invariant; logits O(1); padding contributes exp(0)=1, zero v).
// ---------------------------------------------------------------------------
__global__ __launch_bounds__(256) void k_attn(
    const float* __restrict__ x, float* __restrict__ out)
{
    __shared__ float hs[64 * 65];

    const int tid  = threadIdx.x;
    const int lane = tid & 31;
    const int wid  = tid >> 5;

    const int n0 = blockIdx.x * 64;      // 64 voxels per block, same batch
    const int bb = n0 / NS;
    const int s0 = n0 % NS;

    const int half = lane >> 4;
    const int l4   = lane & 15;
    const int grp  = wid * 2 + half;     // query group 0..15
    const int sg   = s0 + grp * 4;       // first of 4 queries (w-aligned)
    const int d = sg / 576, h = (sg / 24) % 24, w0 = sg % 24;
    const int c0 = l4 * 4;               // quad (l4>>2) = head

    // q for the 4 queries
    u64 q01[4], q23[4];
    {
        const long qa = (long)(bb * NS + sg) * NC + c0;
#pragma unroll
        for (int i = 0; i < 4; i++) {
            ulonglong2 qv = *(const ulonglong2*)(g_q + qa + (long)i * NC);
            q01[i] = qv.x; q23[i] = qv.y;
        }
    }

    // padded base at (d+1, h+1, w0): row j covers padded w0+j; query i's
    // neighbors are rows j in {i, i+1, i+2}. Always in-range (padded).
    const long pb = ((long)bb * P3 + (d + 1) * PD2 + (h + 1) * PD + w0) * NC + c0;

    u64 acc01[4], acc23[4];
    float lsum[4];
#pragma unroll
    for (int i = 0; i < 4; i++) { acc01[i] = 0ull; acc23[i] = 0ull; lsum[i] = 0.0f; }

#pragma unroll
    for (int dh = 0; dh < 9; dh++) {
        const int di = dh / 3 - 1, hi = dh % 3 - 1;
        const long rb = pb + (long)(di * PD2 + hi * PD) * NC;
        const float* kb = g_kp + rb;
        const float* vb = g_vp + rb;
#pragma unroll
        for (int j = 0; j < 6; j++) {
            ulonglong2 kk = *(const ulonglong2*)(kb + j * NC);
            ulonglong2 vv = *(const ulonglong2*)(vb + j * NC);
            const int ilo = (j - 2 > 0) ? j - 2 : 0;
            const int ihi = (j < 3) ? j : 3;
#pragma unroll
            for (int i = ilo; i <= ihi; i++) {
                u64 dd = fma2(q01[i], kk.x, 0ull);
                dd = fma2(q23[i], kk.y, dd);
                float2 df = unpack2(dd);
                float sc = df.x + df.y;
                sc += __shfl_xor_sync(0xffffffffu, sc, 1);
                sc += __shfl_xor_sync(0xffffffffu, sc, 2);
                float p = __expf(sc);
                lsum[i] += p;
                u64 p2 = pack2(p, p);
                acc01[i] = fma2(p2, vv.x, acc01[i]);
                acc23[i] = fma2(p2, vv.y, acc23[i]);
            }
        }
    }

#pragma unroll
    for (int i = 0; i < 4; i++) {
        const float inv = 1.0f / lsum[i];
        float2 a = unpack2(acc01[i]);
        float2 b = unpack2(acc23[i]);
        const int col = grp * 4 + i;
        hs[(c0 + 0) * 65 + col] = a.x * inv;
        hs[(c0 + 1) * 65 + col] = a.y * inv;
        hs[(c0 + 2) * 65 + col] = b.x * inv;
        hs[(c0 + 3) * 65 + col] = b.y * inv;
    }
    __syncthreads();

    // Coalesced channel-major output with residual add (64 vox x 64 ch)
#pragma unroll
    for (int k = 0; k < 16; k++) {
        int idx = tid + k * 256;
        int c = idx >> 6, t = idx & 63;
        long gi = ((long)bb * NC + c) * NS + s0 + t;
        out[gi] = hs[c * 65 + t] + x[gi];
    }
}

// ---------------------------------------------------------------------------
extern "C" void kernel_launch(void* const* d_in, const int* in_sizes, int n_in,
                              void* d_out, int out_size)
{
    const float* x  = (const float*)d_in[0];
    // d_in[1] = cemb (unused by reference forward)
    const float* Wq = (const float*)d_in[2];
    const float* bq = (const float*)d_in[3];
    const float* Wk = (const float*)d_in[4];
    const float* bk = (const float*)d_in[5];
    const float* Wv = (const float*)d_in[6];
    const float* bv = (const float*)d_in[7];
    float* out = (float*)d_out;

    k_proj<<<NPROJ + NZERO, 256>>>(x, Wq, bq, Wk, bk, Wv, bv);
    k_attn<<<NVOX / 64, 256>>>(x, out);
}